// round 4
// baseline (speedup 1.0000x reference)
#include <cuda_runtime.h>
#include <cstdint>

#define MARGIN 1.0f
#define MAX_TRIALS 50
#define BLK 256
#define MAX_B (1 << 20)
#define MAX_NB ((MAX_B + BLK - 1) / BLK)   // 4096

// Scratch (no allocations allowed in kernel_launch)
__device__ float    g_neg_score[MAX_B];  // scores of label-0 examples, stable order
__device__ float    g_pos_score[MAX_B];  // scores of label-1 examples, stable order
__device__ int      g_pos_idx[MAX_B];    // original indices of label-1 examples
__device__ float    g_per[MAX_B];        // per-positive loss contribution
__device__ int      g_queue[MAX_B];      // unresolved positive slots
__device__ unsigned g_flags[MAX_NB];     // lookback: state<<30 | value
__device__ float    g_partials[MAX_NB];
__device__ int      g_num_neg;
__device__ int      g_qcount;
__device__ int      g_done;
__device__ float    g_harm[MAX_TRIALS];

// ---------------- Threefry-2x32 (exact JAX partitionable semantics) --------
__device__ __forceinline__ uint32_t rotl32(uint32_t x, int d) {
    return __funnelshift_l(x, x, d);
}

__device__ __forceinline__ uint32_t jax_random_bits32(uint32_t j) {
    const uint32_t k0 = 0u, k1 = 42u;
    const uint32_t ks2 = k0 ^ k1 ^ 0x1BD11BDAu;
    uint32_t x0 = 0u + k0;          // c0 = hi32(j) = 0
    uint32_t x1 = j + k1;           // c1 = lo32(j)
    const int R0[4] = {13, 15, 26, 6};
    const int R1[4] = {17, 29, 16, 24};
#pragma unroll
    for (int i = 0; i < 4; i++) { x0 += x1; x1 = rotl32(x1, R0[i]); x1 ^= x0; }
    x0 += k1;  x1 += ks2 + 1u;
#pragma unroll
    for (int i = 0; i < 4; i++) { x0 += x1; x1 = rotl32(x1, R1[i]); x1 ^= x0; }
    x0 += ks2; x1 += k0 + 2u;
#pragma unroll
    for (int i = 0; i < 4; i++) { x0 += x1; x1 = rotl32(x1, R0[i]); x1 ^= x0; }
    x0 += k0;  x1 += k1 + 3u;
#pragma unroll
    for (int i = 0; i < 4; i++) { x0 += x1; x1 = rotl32(x1, R1[i]); x1 ^= x0; }
    x0 += k1;  x1 += ks2 + 4u;
#pragma unroll
    for (int i = 0; i < 4; i++) { x0 += x1; x1 = rotl32(x1, R0[i]); x1 ^= x0; }
    x0 += ks2; x1 += k0 + 5u;
    return x0 ^ x1;
}

__device__ __forceinline__ float bits_to_uniform(uint32_t bits) {
    return __uint_as_float((bits >> 9) | 0x3f800000u) - 1.0f;
}

__device__ __forceinline__ float sample_neg(uint32_t j, float nnf, int num_neg) {
    float u = bits_to_uniform(jax_random_bits32(j));
    int idx = (int)(u * nnf);
    idx = min(max(idx, 0), num_neg - 1);
    return __ldg(&g_neg_score[idx]);
}

// ---------------- Pass 1 (fused): single-pass scan + stable partition ------
// Decoupled lookback over per-block zero counts; then scatter neg scores and
// pos (idx, score) in stable order. Flags are zero at entry (reset by the
// previous invocation's reduce_finalize; static zero-init on first call).
__global__ void fused_partition_kernel(const int* __restrict__ labels,
                                       const float* __restrict__ scores,
                                       int B, int nb) {
    int bid = blockIdx.x;
    int tid = threadIdx.x;
    int i = bid * BLK + tid;
    int lane = tid & 31;
    int w = tid >> 5;

    int   lab = (i < B) ? labels[i] : 1;
    float sc  = (i < B) ? scores[i] : 0.0f;
    int f = (i < B && lab == 0) ? 1 : 0;

    unsigned m = __ballot_sync(0xffffffffu, f);
    int wr = __popc(m & ((1u << lane) - 1u));
    __shared__ int woff[BLK / 32];
    __shared__ int s_exc;
    if (lane == 0) woff[w] = __popc(m);
    __syncthreads();

    if (tid == 0) {
        int bc = 0;
#pragma unroll
        for (int k = 0; k < BLK / 32; k++) { int c = woff[k]; woff[k] = bc; bc += c; }

        int exc = 0;
        if (bid == 0) {
            atomicExch(&g_flags[0], (2u << 30) | (unsigned)bc);
        } else {
            atomicExch(&g_flags[bid], (1u << 30) | (unsigned)bc);
            int j = bid - 1;
            while (true) {
                unsigned v = atomicAdd(&g_flags[j], 0u);
                unsigned st = v >> 30;
                if (st == 0u) { __nanosleep(20); continue; }
                exc += (int)(v & 0x3FFFFFFFu);
                if (st == 2u) break;
                j--;
            }
            atomicExch(&g_flags[bid], (2u << 30) | (unsigned)(exc + bc));
        }
        s_exc = exc;
        if (bid == nb - 1) g_num_neg = exc + bc;
        if (bid == 0) {
            float h = 0.0f;
#pragma unroll
            for (int j2 = 1; j2 <= MAX_TRIALS; j2++) {
                h += __fdiv_rn(1.0f, (float)j2);
                g_harm[j2 - 1] = h;
            }
        }
    }
    __syncthreads();

    if (i < B) {
        int neg_before = s_exc + woff[w] + wr;   // negatives strictly before i
        if (f) {
            g_neg_score[neg_before] = sc;
        } else {
            int ps = i - neg_before;
            g_pos_idx[ps] = i;
            g_pos_score[ps] = sc;
        }
    }
}

// ---------------- Phase 1: first 4 trials, 2 positives/thread (ILP-8) ------
__global__ void phase1_kernel(int B) {
    int tid = threadIdx.x;
    int p0 = blockIdx.x * (2 * BLK) + tid;
    int p1 = p0 + BLK;
    int num_neg = g_num_neg;
    int num_pos = B - num_neg;
    if (p0 >= num_pos) return;
    if (num_neg <= 0) {
        g_per[p0] = 0.0f;
        if (p1 < num_pos) g_per[p1] = 0.0f;
        return;
    }
    float nnf = (float)num_neg;

    bool has1 = (p1 < num_pos);
    int i0 = g_pos_idx[p0];
    int i1 = has1 ? g_pos_idx[p1] : i0;
    float s0 = g_pos_score[p0];
    float s1 = has1 ? g_pos_score[p1] : s0;
    uint32_t jb0 = (uint32_t)i0 * (uint32_t)MAX_TRIALS;
    uint32_t jb1 = (uint32_t)i1 * (uint32_t)MAX_TRIALS;

    float na[4], nbv[4];
#pragma unroll
    for (int k = 0; k < 4; k++) {
        na[k]  = sample_neg(jb0 + (uint32_t)k, nnf, num_neg);
        nbv[k] = sample_neg(jb1 + (uint32_t)k, nnf, num_neg);
    }

    float per0 = 0.0f, per1 = 0.0f;
    bool r0 = false, r1 = false;
#pragma unroll
    for (int k = 0; k < 4; k++) {
        if (!r0 && na[k] + MARGIN > s0) {
            int rank = max(1, MAX_TRIALS / (k + 1));
            per0 = __ldg(&g_harm[rank - 1]) * fmaxf(MARGIN - (s0 - na[k]), 0.0f);
            r0 = true;
        }
        if (!r1 && nbv[k] + MARGIN > s1) {
            int rank = max(1, MAX_TRIALS / (k + 1));
            per1 = __ldg(&g_harm[rank - 1]) * fmaxf(MARGIN - (s1 - nbv[k]), 0.0f);
            r1 = true;
        }
    }
    g_per[p0] = per0;
    if (has1) g_per[p1] = per1;
    if (!r0) { int q = atomicAdd(&g_qcount, 1); g_queue[q] = p0; }
    if (has1 && !r1) { int q = atomicAdd(&g_qcount, 1); g_queue[q] = p1; }
}

// ---------------- Phase 2: trials 4..49 for unresolved (dense) -------------
__global__ void phase2_kernel() {
    int n = g_qcount;
    int num_neg = g_num_neg;
    float nnf = (float)num_neg;
    for (int q = blockIdx.x * blockDim.x + threadIdx.x; q < n;
         q += gridDim.x * blockDim.x) {
        int p = g_queue[q];
        int i = g_pos_idx[p];
        float s = g_pos_score[p];
        uint32_t jb = (uint32_t)i * (uint32_t)MAX_TRIALS;
        float per = 0.0f;
        bool done = false;
#pragma unroll 1
        for (int tb = 4; tb < MAX_TRIALS && !done; tb += 4) {
            float ns[4];
            int nk = min(4, MAX_TRIALS - tb);
#pragma unroll
            for (int k = 0; k < 4; k++)
                if (k < nk) ns[k] = sample_neg(jb + (uint32_t)(tb + k), nnf, num_neg);
#pragma unroll
            for (int k = 0; k < 4; k++) {
                if (!done && k < nk && ns[k] + MARGIN > s) {
                    int t = tb + k;
                    int rank = max(1, MAX_TRIALS / (t + 1));
                    per = __ldg(&g_harm[rank - 1]) * fmaxf(MARGIN - (s - ns[k]), 0.0f);
                    done = true;
                }
            }
        }
        if (done) g_per[p] = per;   // else stays 0 from phase 1
    }
}

// ---------------- Reduce + finalize (last-block) + state reset -------------
__global__ void reduce_finalize_kernel(float* __restrict__ out, int nb, int B) {
    __shared__ float red[BLK];
    __shared__ bool s_last;
    int tid = threadIdx.x;
    int p = blockIdx.x * BLK + tid;
    int num_pos = B - g_num_neg;
    red[tid] = (p < num_pos) ? g_per[p] : 0.0f;
    __syncthreads();
    for (int off = BLK / 2; off > 0; off >>= 1) {
        if (tid < off) red[tid] += red[tid + off];
        __syncthreads();
    }
    if (tid == 0) {
        g_partials[blockIdx.x] = red[0];
        __threadfence();
        int t = atomicAdd(&g_done, 1);
        s_last = (t == gridDim.x - 1);
    }
    __syncthreads();
    if (!s_last) return;

    // Last block: deterministic final sum (fixed strided order), then reset
    float s = 0.0f;
    for (int k = tid; k < nb; k += BLK) s += g_partials[k];
    __syncthreads();
    red[tid] = s;
    __syncthreads();
    for (int off = BLK / 2; off > 0; off >>= 1) {
        if (tid < off) red[tid] += red[tid + off];
        __syncthreads();
    }
    if (tid == 0) {
        int nn = g_num_neg;
        int np = B - nn;
        out[0] = (nn > 0 && np > 0) ? red[0] / (float)np : 0.0f;
        g_done = 0;
        g_qcount = 0;
    }
    // reset lookback flags for the next invocation (graph replay)
    for (int k = tid; k < nb; k += BLK) g_flags[k] = 0u;
}

extern "C" void kernel_launch(void* const* d_in, const int* in_sizes, int n_in,
                              void* d_out, int out_size) {
    const float* scores = (const float*)d_in[0];
    const int*   labels = (const int*)d_in[1];
    float* out = (float*)d_out;
    int B  = in_sizes[0];
    int nb = (B + BLK - 1) / BLK;
    int nb2 = (B + 2 * BLK - 1) / (2 * BLK);

    fused_partition_kernel<<<nb, BLK>>>(labels, scores, B, nb);
    phase1_kernel<<<nb2, BLK>>>(B);
    phase2_kernel<<<296, BLK>>>();
    reduce_finalize_kernel<<<nb, BLK>>>(out, nb, B);
}

// round 5
// speedup vs baseline: 1.6600x; 1.6600x over previous
#include <cuda_runtime.h>
#include <cstdint>

#define MARGIN 1.0f
#define MAX_TRIALS 50
#define BLK 256
#define MAX_B (1 << 20)
#define MAX_NB ((MAX_B + BLK - 1) / BLK)   // 4096

// Scratch (no allocations allowed in kernel_launch)
__device__ float g_neg_score[MAX_B];   // scores of label-0 examples, stable order
__device__ float g_pos_score[MAX_B];   // scores of label-1 examples, stable order
__device__ int   g_pos_idx[MAX_B];     // original indices of label-1 examples
__device__ float g_per[MAX_B];         // per-positive loss contribution
__device__ int   g_queue[MAX_B];       // unresolved positive slots
__device__ int   g_blockcnt[MAX_NB];
__device__ int   g_num_neg;
__device__ int   g_qcount;
__device__ float g_harm[MAX_TRIALS];
__device__ float g_partials[MAX_NB];

// ---------------- Threefry-2x32 (exact JAX partitionable semantics) --------
__device__ __forceinline__ uint32_t rotl32(uint32_t x, int d) {
    return __funnelshift_l(x, x, d);
}

__device__ __forceinline__ uint32_t jax_random_bits32(uint32_t j) {
    const uint32_t k0 = 0u, k1 = 42u;
    const uint32_t ks2 = k0 ^ k1 ^ 0x1BD11BDAu;
    uint32_t x0 = 0u + k0;          // c0 = hi32(j) = 0
    uint32_t x1 = j + k1;           // c1 = lo32(j)
    const int R0[4] = {13, 15, 26, 6};
    const int R1[4] = {17, 29, 16, 24};
#pragma unroll
    for (int i = 0; i < 4; i++) { x0 += x1; x1 = rotl32(x1, R0[i]); x1 ^= x0; }
    x0 += k1;  x1 += ks2 + 1u;
#pragma unroll
    for (int i = 0; i < 4; i++) { x0 += x1; x1 = rotl32(x1, R1[i]); x1 ^= x0; }
    x0 += ks2; x1 += k0 + 2u;
#pragma unroll
    for (int i = 0; i < 4; i++) { x0 += x1; x1 = rotl32(x1, R0[i]); x1 ^= x0; }
    x0 += k0;  x1 += k1 + 3u;
#pragma unroll
    for (int i = 0; i < 4; i++) { x0 += x1; x1 = rotl32(x1, R1[i]); x1 ^= x0; }
    x0 += k1;  x1 += ks2 + 4u;
#pragma unroll
    for (int i = 0; i < 4; i++) { x0 += x1; x1 = rotl32(x1, R0[i]); x1 ^= x0; }
    x0 += ks2; x1 += k0 + 5u;
    return x0 ^ x1;
}

__device__ __forceinline__ float bits_to_uniform(uint32_t bits) {
    return __uint_as_float((bits >> 9) | 0x3f800000u) - 1.0f;
}

__device__ __forceinline__ float sample_neg(uint32_t j, float nnf, int num_neg) {
    float u = bits_to_uniform(jax_random_bits32(j));
    int idx = (int)(u * nnf);
    idx = min(max(idx, 0), num_neg - 1);
    return __ldg(&g_neg_score[idx]);
}

// ---------------- Pass 1: per-block count of label==0 ----------------
__global__ void count_zeros_kernel(const int* __restrict__ labels, int B) {
    int i = blockIdx.x * BLK + threadIdx.x;
    int f = (i < B && labels[i] == 0) ? 1 : 0;
    unsigned m = __ballot_sync(0xffffffffu, f);
    __shared__ int wsum[BLK / 32];
    if ((threadIdx.x & 31) == 0) wsum[threadIdx.x >> 5] = __popc(m);
    __syncthreads();
    if (threadIdx.x == 0) {
        int s = 0;
#pragma unroll
        for (int w = 0; w < BLK / 32; w++) s += wsum[w];
        g_blockcnt[blockIdx.x] = s;
    }
}

// ---------------- Pass 2: exclusive scan + per-replay init -----------------
__global__ void scan_blocks_kernel(int nb) {
    __shared__ int sh[1024];
    int t = threadIdx.x;
    int v[4];
    int base = t * 4;
    int s = 0;
#pragma unroll
    for (int k = 0; k < 4; k++) {
        int idx = base + k;
        v[k] = (idx < nb) ? g_blockcnt[idx] : 0;
        s += v[k];
    }
    sh[t] = s;
    __syncthreads();
    for (int off = 1; off < 1024; off <<= 1) {
        int y = (t >= off) ? sh[t - off] : 0;
        __syncthreads();
        sh[t] += y;
        __syncthreads();
    }
    int run = (t > 0) ? sh[t - 1] : 0;
#pragma unroll
    for (int k = 0; k < 4; k++) {
        int idx = base + k;
        if (idx < nb) {
            int c = v[k];
            g_blockcnt[idx] = run;
            run += c;
        }
    }
    if (t == 0) {
        g_num_neg = sh[1023];
        g_qcount = 0;
        float h = 0.0f;
#pragma unroll
        for (int j = 1; j <= MAX_TRIALS; j++) {
            h += __fdiv_rn(1.0f, (float)j);
            g_harm[j - 1] = h;
        }
    }
}

// ---------------- Pass 3: scatter neg scores + pos (idx,score), stable -----
__global__ void scatter_kernel(const int* __restrict__ labels,
                               const float* __restrict__ scores, int B) {
    int i = blockIdx.x * BLK + threadIdx.x;
    int lane = threadIdx.x & 31;
    int w = threadIdx.x >> 5;
    int   lab = (i < B) ? labels[i] : 1;
    float sc  = (i < B) ? scores[i] : 0.0f;
    int f = (i < B && lab == 0) ? 1 : 0;
    unsigned m = __ballot_sync(0xffffffffu, f);
    int wr = __popc(m & ((1u << lane) - 1u));
    __shared__ int woff[BLK / 32];
    if (lane == 0) woff[w] = __popc(m);
    __syncthreads();
    if (threadIdx.x == 0) {
        int r = 0;
#pragma unroll
        for (int k = 0; k < BLK / 32; k++) { int c = woff[k]; woff[k] = r; r += c; }
    }
    __syncthreads();
    if (i < B) {
        int neg_before = g_blockcnt[blockIdx.x] + woff[w] + wr;  // negs strictly before i
        if (f) {
            g_neg_score[neg_before] = sc;
        } else {
            int ps = i - neg_before;
            g_pos_idx[ps] = i;
            g_pos_score[ps] = sc;
        }
    }
}

// ---------------- Phase 1: first 4 trials, 2 positives/thread (ILP-8) ------
__global__ void phase1_kernel(int B) {
    int tid = threadIdx.x;
    int p0 = blockIdx.x * (2 * BLK) + tid;
    int p1 = p0 + BLK;
    int num_neg = g_num_neg;
    int num_pos = B - num_neg;
    if (p0 >= num_pos) return;
    if (num_neg <= 0) {
        g_per[p0] = 0.0f;
        if (p1 < num_pos) g_per[p1] = 0.0f;
        return;
    }
    float nnf = (float)num_neg;

    bool has1 = (p1 < num_pos);
    int i0 = g_pos_idx[p0];
    int i1 = has1 ? g_pos_idx[p1] : i0;
    float s0 = g_pos_score[p0];
    float s1 = has1 ? g_pos_score[p1] : s0;
    uint32_t jb0 = (uint32_t)i0 * (uint32_t)MAX_TRIALS;
    uint32_t jb1 = (uint32_t)i1 * (uint32_t)MAX_TRIALS;

    float na[4], nbv[4];
#pragma unroll
    for (int k = 0; k < 4; k++) {
        na[k]  = sample_neg(jb0 + (uint32_t)k, nnf, num_neg);
        nbv[k] = sample_neg(jb1 + (uint32_t)k, nnf, num_neg);
    }

    float per0 = 0.0f, per1 = 0.0f;
    bool r0 = false, r1 = false;
#pragma unroll
    for (int k = 0; k < 4; k++) {
        if (!r0 && na[k] + MARGIN > s0) {
            int rank = max(1, MAX_TRIALS / (k + 1));
            per0 = __ldg(&g_harm[rank - 1]) * fmaxf(MARGIN - (s0 - na[k]), 0.0f);
            r0 = true;
        }
        if (!r1 && nbv[k] + MARGIN > s1) {
            int rank = max(1, MAX_TRIALS / (k + 1));
            per1 = __ldg(&g_harm[rank - 1]) * fmaxf(MARGIN - (s1 - nbv[k]), 0.0f);
            r1 = true;
        }
    }
    g_per[p0] = per0;
    if (has1) g_per[p1] = per1;
    if (!r0) { int q = atomicAdd(&g_qcount, 1); g_queue[q] = p0; }
    if (has1 && !r1) { int q = atomicAdd(&g_qcount, 1); g_queue[q] = p1; }
}

// ---------------- Phase 2: trials 4..49 for unresolved (dense) -------------
__global__ void phase2_kernel() {
    int n = g_qcount;
    int num_neg = g_num_neg;
    float nnf = (float)num_neg;
    for (int q = blockIdx.x * blockDim.x + threadIdx.x; q < n;
         q += gridDim.x * blockDim.x) {
        int p = g_queue[q];
        int i = g_pos_idx[p];
        float s = g_pos_score[p];
        uint32_t jb = (uint32_t)i * (uint32_t)MAX_TRIALS;
        float per = 0.0f;
        bool done = false;
#pragma unroll 1
        for (int tb = 4; tb < MAX_TRIALS && !done; tb += 4) {
            float ns[4];
            int nk = min(4, MAX_TRIALS - tb);
#pragma unroll
            for (int k = 0; k < 4; k++)
                if (k < nk) ns[k] = sample_neg(jb + (uint32_t)(tb + k), nnf, num_neg);
#pragma unroll
            for (int k = 0; k < 4; k++) {
                if (!done && k < nk && ns[k] + MARGIN > s) {
                    int t = tb + k;
                    int rank = max(1, MAX_TRIALS / (t + 1));
                    per = __ldg(&g_harm[rank - 1]) * fmaxf(MARGIN - (s - ns[k]), 0.0f);
                    done = true;
                }
            }
        }
        if (done) g_per[p] = per;   // else stays 0 from phase 1
    }
}

// ---------------- Reduce: per-block partials over positives ----------------
__global__ void reduce_kernel(int B) {
    __shared__ float red[BLK];
    int p = blockIdx.x * BLK + threadIdx.x;
    int num_pos = B - g_num_neg;
    red[threadIdx.x] = (p < num_pos) ? g_per[p] : 0.0f;
    __syncthreads();
    for (int off = BLK / 2; off > 0; off >>= 1) {
        if (threadIdx.x < off) red[threadIdx.x] += red[threadIdx.x + off];
        __syncthreads();
    }
    if (threadIdx.x == 0) g_partials[blockIdx.x] = red[0];
}

// ---------------- Finalize -------------------------------------------------
__global__ void finalize_kernel(float* __restrict__ out, int nb, int B) {
    __shared__ float red[1024];
    float s = 0.0f;
    for (int k = threadIdx.x; k < nb; k += 1024) s += g_partials[k];
    red[threadIdx.x] = s;
    __syncthreads();
    for (int off = 512; off > 0; off >>= 1) {
        if (threadIdx.x < off) red[threadIdx.x] += red[threadIdx.x + off];
        __syncthreads();
    }
    if (threadIdx.x == 0) {
        int nn = g_num_neg;
        int np = B - nn;
        out[0] = (nn > 0 && np > 0) ? red[0] / (float)np : 0.0f;
    }
}

extern "C" void kernel_launch(void* const* d_in, const int* in_sizes, int n_in,
                              void* d_out, int out_size) {
    const float* scores = (const float*)d_in[0];
    const int*   labels = (const int*)d_in[1];
    float* out = (float*)d_out;
    int B  = in_sizes[0];
    int nb = (B + BLK - 1) / BLK;
    int nb2 = (B + 2 * BLK - 1) / (2 * BLK);

    count_zeros_kernel<<<nb, BLK>>>(labels, B);
    scan_blocks_kernel<<<1, 1024>>>(nb);
    scatter_kernel<<<nb, BLK>>>(labels, scores, B);
    phase1_kernel<<<nb2, BLK>>>(B);
    phase2_kernel<<<296, BLK>>>();
    reduce_kernel<<<nb, BLK>>>(B);
    finalize_kernel<<<1, 1024>>>(out, nb, B);
}

// round 6
// speedup vs baseline: 1.8996x; 1.1444x over previous
#include <cuda_runtime.h>
#include <cstdint>

#define MARGIN 1.0f
#define MAX_TRIALS 50
#define P1_TRIALS 2
#define BLK 256
#define MAX_B (1 << 20)
#define MAX_NB ((MAX_B + BLK - 1) / BLK)   // 4096

// Scratch (no allocations allowed in kernel_launch)
__device__ float g_neg_score[MAX_B];   // scores of label-0 examples, stable order
__device__ float g_pos_score[MAX_B];   // scores of label-1 examples, stable order
__device__ int   g_pos_idx[MAX_B];     // original indices of label-1 examples
__device__ int   g_queue[MAX_B];       // unresolved positive slots
__device__ int   g_blockcnt[MAX_NB];
__device__ float g_partials[MAX_NB];
__device__ int   g_num_neg;
__device__ int   g_qcount;
__device__ float g_extra;
__device__ float g_harm[MAX_TRIALS];

// ---------------- Threefry-2x32 (exact JAX partitionable semantics) --------
__device__ __forceinline__ uint32_t rotl32(uint32_t x, int d) {
    return __funnelshift_l(x, x, d);
}

__device__ __forceinline__ uint32_t jax_random_bits32(uint32_t j) {
    const uint32_t k0 = 0u, k1 = 42u;
    const uint32_t ks2 = k0 ^ k1 ^ 0x1BD11BDAu;
    uint32_t x0 = 0u + k0;          // c0 = hi32(j) = 0
    uint32_t x1 = j + k1;           // c1 = lo32(j)
    const int R0[4] = {13, 15, 26, 6};
    const int R1[4] = {17, 29, 16, 24};
#pragma unroll
    for (int i = 0; i < 4; i++) { x0 += x1; x1 = rotl32(x1, R0[i]); x1 ^= x0; }
    x0 += k1;  x1 += ks2 + 1u;
#pragma unroll
    for (int i = 0; i < 4; i++) { x0 += x1; x1 = rotl32(x1, R1[i]); x1 ^= x0; }
    x0 += ks2; x1 += k0 + 2u;
#pragma unroll
    for (int i = 0; i < 4; i++) { x0 += x1; x1 = rotl32(x1, R0[i]); x1 ^= x0; }
    x0 += k0;  x1 += k1 + 3u;
#pragma unroll
    for (int i = 0; i < 4; i++) { x0 += x1; x1 = rotl32(x1, R1[i]); x1 ^= x0; }
    x0 += k1;  x1 += ks2 + 4u;
#pragma unroll
    for (int i = 0; i < 4; i++) { x0 += x1; x1 = rotl32(x1, R0[i]); x1 ^= x0; }
    x0 += ks2; x1 += k0 + 5u;
    return x0 ^ x1;
}

__device__ __forceinline__ float bits_to_uniform(uint32_t bits) {
    return __uint_as_float((bits >> 9) | 0x3f800000u) - 1.0f;
}

__device__ __forceinline__ float sample_neg(uint32_t j, float nnf, int num_neg) {
    float u = bits_to_uniform(jax_random_bits32(j));
    int idx = (int)(u * nnf);
    idx = min(max(idx, 0), num_neg - 1);
    return __ldg(&g_neg_score[idx]);
}

// ---------------- Pass 1: per-block count of label==0 ----------------
__global__ void count_zeros_kernel(const int* __restrict__ labels, int B) {
    int i = blockIdx.x * BLK + threadIdx.x;
    int f = (i < B && labels[i] == 0) ? 1 : 0;
    unsigned m = __ballot_sync(0xffffffffu, f);
    __shared__ int wsum[BLK / 32];
    if ((threadIdx.x & 31) == 0) wsum[threadIdx.x >> 5] = __popc(m);
    __syncthreads();
    if (threadIdx.x == 0) {
        int s = 0;
#pragma unroll
        for (int w = 0; w < BLK / 32; w++) s += wsum[w];
        g_blockcnt[blockIdx.x] = s;
    }
}

// ---------------- Pass 2: exclusive scan + per-replay init -----------------
__global__ void scan_blocks_kernel(int nb) {
    __shared__ int sh[1024];
    int t = threadIdx.x;
    int v[4];
    int base = t * 4;
    int s = 0;
#pragma unroll
    for (int k = 0; k < 4; k++) {
        int idx = base + k;
        v[k] = (idx < nb) ? g_blockcnt[idx] : 0;
        s += v[k];
    }
    sh[t] = s;
    __syncthreads();
    for (int off = 1; off < 1024; off <<= 1) {
        int y = (t >= off) ? sh[t - off] : 0;
        __syncthreads();
        sh[t] += y;
        __syncthreads();
    }
    int run = (t > 0) ? sh[t - 1] : 0;
#pragma unroll
    for (int k = 0; k < 4; k++) {
        int idx = base + k;
        if (idx < nb) {
            int c = v[k];
            g_blockcnt[idx] = run;
            run += c;
        }
    }
    if (t == 0) {
        g_num_neg = sh[1023];
        g_qcount = 0;
        g_extra = 0.0f;
        float h = 0.0f;
#pragma unroll
        for (int j = 1; j <= MAX_TRIALS; j++) {
            h += __fdiv_rn(1.0f, (float)j);
            g_harm[j - 1] = h;
        }
    }
}

// ---------------- Pass 3: scatter neg scores + pos (idx,score), stable -----
__global__ void scatter_kernel(const int* __restrict__ labels,
                               const float* __restrict__ scores, int B) {
    int i = blockIdx.x * BLK + threadIdx.x;
    int lane = threadIdx.x & 31;
    int w = threadIdx.x >> 5;
    int   lab = (i < B) ? labels[i] : 1;
    float sc  = (i < B) ? scores[i] : 0.0f;
    int f = (i < B && lab == 0) ? 1 : 0;
    unsigned m = __ballot_sync(0xffffffffu, f);
    int wr = __popc(m & ((1u << lane) - 1u));
    __shared__ int woff[BLK / 32];
    if (lane == 0) woff[w] = __popc(m);
    __syncthreads();
    if (threadIdx.x == 0) {
        int r = 0;
#pragma unroll
        for (int k = 0; k < BLK / 32; k++) { int c = woff[k]; woff[k] = r; r += c; }
    }
    __syncthreads();
    if (i < B) {
        int neg_before = g_blockcnt[blockIdx.x] + woff[w] + wr;  // negs strictly before i
        if (f) {
            g_neg_score[neg_before] = sc;
        } else {
            int ps = i - neg_before;
            g_pos_idx[ps] = i;
            g_pos_score[ps] = sc;
        }
    }
}

// ---------------- Phase 1: first 2 trials + fused block reduction ----------
__global__ void phase1_kernel(int B) {
    __shared__ float red[BLK];
    int tid = threadIdx.x;
    int p = blockIdx.x * BLK + tid;
    int num_neg = g_num_neg;
    int num_pos = B - num_neg;

    float per = 0.0f;
    if (p < num_pos && num_neg > 0) {
        int i = g_pos_idx[p];
        float s = g_pos_score[p];
        float nnf = (float)num_neg;
        uint32_t jb = (uint32_t)i * (uint32_t)MAX_TRIALS;

        float ns[P1_TRIALS];
#pragma unroll
        for (int k = 0; k < P1_TRIALS; k++)
            ns[k] = sample_neg(jb + (uint32_t)k, nnf, num_neg);

        bool resolved = false;
#pragma unroll
        for (int k = 0; k < P1_TRIALS; k++) {
            if (!resolved && ns[k] + MARGIN > s) {
                int rank = max(1, MAX_TRIALS / (k + 1));
                per = __ldg(&g_harm[rank - 1]) * fmaxf(MARGIN - (s - ns[k]), 0.0f);
                resolved = true;
            }
        }
        if (!resolved) {
            int q = atomicAdd(&g_qcount, 1);
            g_queue[q] = p;
        }
    }

    // deterministic in-block reduction of resolved contributions
    red[tid] = per;
    __syncthreads();
    for (int off = BLK / 2; off > 0; off >>= 1) {
        if (tid < off) red[tid] += red[tid + off];
        __syncthreads();
    }
    if (tid == 0) g_partials[blockIdx.x] = red[0];
}

// ---------------- Phase 2: trials 2..49 for unresolved (dense) -------------
__global__ void phase2_kernel() {
    int n = g_qcount;
    int num_neg = g_num_neg;
    float nnf = (float)num_neg;
    float acc = 0.0f;
    for (int q = blockIdx.x * blockDim.x + threadIdx.x; q < n;
         q += gridDim.x * blockDim.x) {
        int p = g_queue[q];
        int i = g_pos_idx[p];
        float s = g_pos_score[p];
        uint32_t jb = (uint32_t)i * (uint32_t)MAX_TRIALS;
        bool done = false;
#pragma unroll 1
        for (int tb = P1_TRIALS; tb < MAX_TRIALS && !done; tb += 4) {
            float ns[4];
            int nk = min(4, MAX_TRIALS - tb);
#pragma unroll
            for (int k = 0; k < 4; k++)
                if (k < nk) ns[k] = sample_neg(jb + (uint32_t)(tb + k), nnf, num_neg);
#pragma unroll
            for (int k = 0; k < 4; k++) {
                if (!done && k < nk && ns[k] + MARGIN > s) {
                    int t = tb + k;
                    int rank = max(1, MAX_TRIALS / (t + 1));
                    acc += __ldg(&g_harm[rank - 1]) * fmaxf(MARGIN - (s - ns[k]), 0.0f);
                    done = true;
                }
            }
        }
    }
    // warp-reduce then one atomic per warp
#pragma unroll
    for (int off = 16; off > 0; off >>= 1)
        acc += __shfl_down_sync(0xffffffffu, acc, off);
    if ((threadIdx.x & 31) == 0 && acc != 0.0f) atomicAdd(&g_extra, acc);
}

// ---------------- Finalize -------------------------------------------------
__global__ void finalize_kernel(float* __restrict__ out, int nb, int B) {
    __shared__ float red[1024];
    float s = 0.0f;
    for (int k = threadIdx.x; k < nb; k += 1024) s += g_partials[k];
    red[threadIdx.x] = s;
    __syncthreads();
    for (int off = 512; off > 0; off >>= 1) {
        if (threadIdx.x < off) red[threadIdx.x] += red[threadIdx.x + off];
        __syncthreads();
    }
    if (threadIdx.x == 0) {
        int nn = g_num_neg;
        int np = B - nn;
        float total = red[0] + g_extra;
        out[0] = (nn > 0 && np > 0) ? total / (float)np : 0.0f;
    }
}

extern "C" void kernel_launch(void* const* d_in, const int* in_sizes, int n_in,
                              void* d_out, int out_size) {
    const float* scores = (const float*)d_in[0];
    const int*   labels = (const int*)d_in[1];
    float* out = (float*)d_out;
    int B  = in_sizes[0];
    int nb = (B + BLK - 1) / BLK;

    count_zeros_kernel<<<nb, BLK>>>(labels, B);
    scan_blocks_kernel<<<1, 1024>>>(nb);
    scatter_kernel<<<nb, BLK>>>(labels, scores, B);
    phase1_kernel<<<nb, BLK>>>(B);
    phase2_kernel<<<296, BLK>>>();
    finalize_kernel<<<1, 1024>>>(out, nb, B);
}